// round 5
// baseline (speedup 1.0000x reference)
#include <cuda_runtime.h>

// LIF constant-current encoder, closed-form time-split.
// x: [N] fp32 (N = 512*512). out: voltages [128*N] then spikes [128*N], fp32.
// Recurrence v_{t+1} = 0.9 v + 0.1 x from v=0 gives v_t = x(1 - 0.9^t) between
// resets. Threshold is strict (v - 1 > 0) and v_t < x, so x <= 1 never spikes:
// whole trajectory is closed-form, z == 0. Each chunk-CTA needs only the
// scalar 0.9^t0 — no replay. x > 1 (absent in this dataset) uses exact replay.

#define SEQ_LENGTH 128
#define CHUNK      16
#define NCHUNKS    (SEQ_LENGTH / CHUNK)
#define ALPHA      0.1f
#define DECAY      0.9f
#define DECAY_CHUNK 0.18530201888518410f  // 0.9^16 (double-rounded to fp32 at use)
#define V_TH       1.0f

__device__ __forceinline__ void lif_step(float4& v, const float4& xv, float4& z) {
    v.x = fmaf(ALPHA, xv.x - v.x, v.x);
    v.y = fmaf(ALPHA, xv.y - v.y, v.y);
    v.z = fmaf(ALPHA, xv.z - v.z, v.z);
    v.w = fmaf(ALPHA, xv.w - v.w, v.w);
    z.x = (v.x > V_TH) ? 1.f : 0.f;
    z.y = (v.y > V_TH) ? 1.f : 0.f;
    z.z = (v.z > V_TH) ? 1.f : 0.f;
    z.w = (v.w > V_TH) ? 1.f : 0.f;
    v.x = (z.x != 0.f) ? 0.f : v.x;
    v.y = (z.y != 0.f) ? 0.f : v.y;
    v.z = (z.z != 0.f) ? 0.f : v.z;
    v.w = (z.w != 0.f) ? 0.f : v.w;
}

__global__ __launch_bounds__(256)
void lif_encoder_kernel(const float* __restrict__ x,
                        float* __restrict__ out,
                        int n4 /* N/4 */, int n /* N */) {
    int i = blockIdx.x * blockDim.x + threadIdx.x;
    if (i >= n4) return;
    int t0 = blockIdx.y * CHUNK;

    float4 xv = reinterpret_cast<const float4*>(x)[i];

    float4* vp = reinterpret_cast<float4*>(out) + (size_t)t0 * n4 + i;
    float4* zp = reinterpret_cast<float4*>(out + (size_t)SEQ_LENGTH * n)
                 + (size_t)t0 * n4 + i;

    float xmax = fmaxf(fmaxf(xv.x, xv.y), fmaxf(xv.z, xv.w));

    if (xmax <= 1.0f) {
        // Fast path: no spikes ever. v_t = x * (1 - 0.9^t), z = 0.
        // p = 0.9^t0 = (0.9^CHUNK)^blockIdx.y  (<= 7 multiplies, uniform)
        float p = 1.0f;
        #pragma unroll 1
        for (unsigned c = blockIdx.y; c > 0; --c) p *= (float)DECAY_CHUNK;

        const float4 zero = make_float4(0.f, 0.f, 0.f, 0.f);
        #pragma unroll
        for (int t = 0; t < CHUNK; ++t) {
            p *= DECAY;                            // p = 0.9^(t0+t+1)
            float4 v;
            v.x = fmaf(-p, xv.x, xv.x);
            v.y = fmaf(-p, xv.y, xv.y);
            v.z = fmaf(-p, xv.z, xv.z);
            v.w = fmaf(-p, xv.w, xv.w);
            __stcs(vp, v);
            __stcs(zp, zero);
            vp += n4;
            zp += n4;
        }
    } else {
        // General path: exact replay recurrence (spiking possible).
        float4 v = make_float4(0.f, 0.f, 0.f, 0.f);
        float4 z;
        for (int t = 0; t < t0; ++t)
            lif_step(v, xv, z);
        #pragma unroll
        for (int t = 0; t < CHUNK; ++t) {
            lif_step(v, xv, z);
            __stcs(vp, v);
            __stcs(zp, z);
            vp += n4;
            zp += n4;
        }
    }
}

extern "C" void kernel_launch(void* const* d_in, const int* in_sizes, int n_in,
                              void* d_out, int out_size) {
    const float* x = (const float*)d_in[0];
    float* out = (float*)d_out;
    int n = in_sizes[0];       // 262144
    int n4 = n / 4;            // 65536

    dim3 block(256);
    dim3 grid((n4 + 255) / 256, NCHUNKS);
    lif_encoder_kernel<<<grid, block>>>(x, out, n4, n);
}